// round 12
// baseline (speedup 1.0000x reference)
#include <cuda_runtime.h>
#include <cuda_fp16.h>
#include <math.h>
#include <float.h>
#include <stdint.h>

// Problem constants (fixed by the dataset)
#define LL 4
#define BB 256
#define CC 512
#define SS 64
#define NPTS 50000
#define KSEL 21   // k+1 smallest needed

// -------- scratch (static device globals; no runtime allocation) --------
__device__ float  g_q[LL * BB * CC];             // 2 MB (fp32 q)
__device__ __half g_q_h[LL * BB * CC];           // 1 MB (fp16 q)
__device__ float  g_q2[LL * BB];
__device__ __half g_bank_h[(size_t)LL * NPTS * CC];  // 204.8 MB (fp16 bank)
__device__ float  g_b2[LL * NPTS];
__device__ float  g_d2[(size_t)LL * BB * NPTS];      // 204.8 MB

// ============================================================
// helpers
// ============================================================
__device__ __forceinline__ uint32_t smem_u32(const void* p) {
    uint32_t a;
    asm("{ .reg .u64 t; cvta.to.shared.u64 t, %1; cvt.u32.u64 %0, t; }"
        : "=r"(a) : "l"(p));
    return a;
}
__device__ __forceinline__ uint32_t h2pack(float a, float b) {
    __half2 h = __floats2half2_rn(a, b);
    return *(uint32_t*)&h;
}
__device__ __forceinline__ void cp16(uint32_t dst, const void* src, int srcsz) {
    asm volatile("cp.async.cg.shared.global [%0], [%1], 16, %2;"
                 :: "r"(dst), "l"(src), "r"(srcsz));
}
__device__ __forceinline__ void mma_f16(float* c, const uint32_t* a, const uint32_t* b) {
    asm volatile(
        "mma.sync.aligned.m16n8k16.row.col.f32.f16.f16.f32 "
        "{%0,%1,%2,%3}, {%4,%5,%6,%7}, {%8,%9}, {%0,%1,%2,%3};"
        : "+f"(c[0]), "+f"(c[1]), "+f"(c[2]), "+f"(c[3])
        : "r"(a[0]), "r"(a[1]), "r"(a[2]), "r"(a[3]), "r"(b[0]), "r"(b[1]));
}

// ============================================================
// Kernel 1: q[l,b,c] = mean_s feats[l,b,c,s]   (one warp per row of 64)
// ============================================================
__global__ void qmean_kernel(const float* __restrict__ feats) {
    int gw = (blockIdx.x * blockDim.x + threadIdx.x) >> 5;
    int lane = threadIdx.x & 31;
    if (gw >= LL * BB * CC) return;
    const float* p = feats + (size_t)gw * SS;
    float s = p[lane] + p[lane + 32];
    #pragma unroll
    for (int o = 16; o > 0; o >>= 1) s += __shfl_xor_sync(0xFFFFFFFFu, s, o);
    if (lane == 0) g_q[gw] = s * (1.0f / 64.0f);
}

// ============================================================
// Kernel 2: row convert fp32 -> fp16 + sum-of-squares (1 warp / 512-row)
// ============================================================
__device__ __forceinline__ void rowcvt_body(const float* __restrict__ src,
                                            __half* __restrict__ dst,
                                            float* __restrict__ ssq_out,
                                            int nrows) {
    int gw = (blockIdx.x * blockDim.x + threadIdx.x) >> 5;
    int lane = threadIdx.x & 31;
    if (gw >= nrows) return;
    const float4* s4 = (const float4*)(src + (size_t)gw * CC) + lane * 4;
    float4 v0 = s4[0], v1 = s4[1], v2 = s4[2], v3 = s4[3];
    float ss = 0.f;
    ss = fmaf(v0.x, v0.x, ss); ss = fmaf(v0.y, v0.y, ss);
    ss = fmaf(v0.z, v0.z, ss); ss = fmaf(v0.w, v0.w, ss);
    ss = fmaf(v1.x, v1.x, ss); ss = fmaf(v1.y, v1.y, ss);
    ss = fmaf(v1.z, v1.z, ss); ss = fmaf(v1.w, v1.w, ss);
    ss = fmaf(v2.x, v2.x, ss); ss = fmaf(v2.y, v2.y, ss);
    ss = fmaf(v2.z, v2.z, ss); ss = fmaf(v2.w, v2.w, ss);
    ss = fmaf(v3.x, v3.x, ss); ss = fmaf(v3.y, v3.y, ss);
    ss = fmaf(v3.z, v3.z, ss); ss = fmaf(v3.w, v3.w, ss);
    uint4 o0 = make_uint4(h2pack(v0.x, v0.y), h2pack(v0.z, v0.w),
                          h2pack(v1.x, v1.y), h2pack(v1.z, v1.w));
    uint4 o1 = make_uint4(h2pack(v2.x, v2.y), h2pack(v2.z, v2.w),
                          h2pack(v3.x, v3.y), h2pack(v3.z, v3.w));
    uint4* d = (uint4*)(dst + (size_t)gw * CC) + lane * 2;
    d[0] = o0; d[1] = o1;
    #pragma unroll
    for (int o = 16; o > 0; o >>= 1) ss += __shfl_xor_sync(0xFFFFFFFFu, ss, o);
    if (lane == 0) ssq_out[gw] = ss;
}
__global__ void rowcvt_q_kernel() {
    rowcvt_body(g_q, g_q_h, g_q2, LL * BB);
}
__global__ void rowcvt_bank_kernel(const float* __restrict__ bank) {
    rowcvt_body(bank, g_bank_h, g_b2, LL * NPTS);
}

// ============================================================
// Kernel 3: f16 mma GEMM (cp.async 6-stage, barrier per 2 tiles) + d2 epilogue
//   CTA: 128 q rows (m) x 128 bank rows (n), Bk=16 per tile, 256 threads.
//   Even tile i: wait_group 2 (tiles i,i+1 ready), sync, issue i+4,i+5,
//                then mma tiles i and i+1 with no barrier between.
// ============================================================
#define Bb 128
#define Bn 128
#define Bk 16
#define STAGES 6
#define NTILES (CC / Bk)   // 32
#define LDT2 12            // words per row (8 half2 + 4 pad, conflict-free frags)
#define TSZ2 (Bb * LDT2)   // 1536 words per stage per matrix
#define GEMM_DSMEM (STAGES * TSZ2 * 2 * 4)   // 73728 bytes

__global__ __launch_bounds__(256, 2)
void gemm_mma_kernel() {
    extern __shared__ uint32_t smw[];
    uint32_t* As = smw;                       // [stage][m][k/2]
    uint32_t* Bs = smw + STAGES * TSZ2;       // [stage][n][k/2]
    __shared__ float q2s[Bb];
    __shared__ float b2s[Bn];

    const int l  = blockIdx.z;
    const int m0 = blockIdx.x * Bb;
    const int n0 = blockIdx.y * Bn;
    const int nrem = NPTS - n0;

    const int tid  = threadIdx.x;
    const int lane = tid & 31;
    const int wid  = tid >> 5;
    const int wm   = wid & 1;
    const int wn   = wid >> 1;
    const int gr   = lane >> 2;
    const int tg   = lane & 3;

    // cp.async loader mapping: thread t -> row t>>1, 16B-chunk t&1
    const int arow  = tid >> 1;
    const int ahalf = tid & 1;
    const bool bok  = (arow < nrem);
    const int bsz   = bok ? 16 : 0;

    const __half* ga = g_q_h    + ((size_t)(l * BB + m0) + arow) * CC + ahalf * 8;
    const __half* gb = g_bank_h + ((size_t)l * NPTS + n0 + (bok ? arow : 0)) * CC + ahalf * 8;

    const uint32_t as_u32 = smem_u32(As);
    const uint32_t bs_u32 = smem_u32(Bs);
    const uint32_t woff = (uint32_t)(arow * LDT2 + ahalf * 4);   // word offset in tile

    float c[4][4][4];
    #pragma unroll
    for (int i = 0; i < 4; i++)
        #pragma unroll
        for (int j = 0; j < 4; j++)
            #pragma unroll
            for (int t = 0; t < 4; t++) c[i][j][t] = 0.f;

    // issue one tile's cp.asyncs + commit
    auto issue_tile = [&](int t) {
        const uint32_t st = (uint32_t)(t % STAGES) * TSZ2;
        cp16(as_u32 + ((st + woff) << 2), ga + t * Bk, 16);
        cp16(bs_u32 + ((st + woff) << 2), gb + t * Bk, bsz);
        asm volatile("cp.async.commit_group;" ::: "memory");
    };

    // mma one tile from its stage
    auto mma_tile = [&](int t) {
        const uint32_t so = (uint32_t)(t % STAGES) * TSZ2;
        uint32_t a[4][4], b[4][2];
        #pragma unroll
        for (int mt = 0; mt < 4; mt++) {
            int base = so + (wm * 64 + mt * 16 + gr) * LDT2 + tg;
            a[mt][0] = As[base];
            a[mt][1] = As[base + 8 * LDT2];
            a[mt][2] = As[base + 4];
            a[mt][3] = As[base + 8 * LDT2 + 4];
        }
        #pragma unroll
        for (int nt = 0; nt < 4; nt++) {
            int base = so + (wn * 32 + nt * 8 + gr) * LDT2 + tg;
            b[nt][0] = Bs[base];
            b[nt][1] = Bs[base + 4];
        }
        #pragma unroll
        for (int mt = 0; mt < 4; mt++)
            #pragma unroll
            for (int nt = 0; nt < 4; nt++)
                mma_f16(c[mt][nt], a[mt], b[nt]);
    };

    // ---- prologue: issue tiles 0..3 (4 groups in flight) ----
    #pragma unroll
    for (int t = 0; t < 4; t++) issue_tile(t);

    // ---- mainloop: step 2 tiles per barrier ----
    #pragma unroll 1
    for (int i = 0; i < NTILES; i += 2) {
        // tiles i..i+3 outstanding; wait until <=2 remain -> tiles i, i+1 done
        asm volatile("cp.async.wait_group 2;" ::: "memory");
        __syncthreads();
        if (i + 4 < NTILES) issue_tile(i + 4);
        if (i + 5 < NTILES) issue_tile(i + 5);
        mma_tile(i);
        mma_tile(i + 1);
    }

    // ---- stage q2 / b2 ----
    __syncthreads();
    if (tid < Bb) {
        q2s[tid] = g_q2[l * BB + m0 + tid];
        b2s[tid] = (n0 + tid < NPTS) ? g_b2[(size_t)l * NPTS + n0 + tid] : 0.f;
    }
    __syncthreads();

    // ---- epilogue ----
    #pragma unroll
    for (int mt = 0; mt < 4; mt++) {
        int ml = wm * 64 + mt * 16 + gr;
        float q2a = q2s[ml];
        float q2b = q2s[ml + 8];
        #pragma unroll
        for (int nt = 0; nt < 4; nt++) {
            int nl = wn * 32 + nt * 8 + 2 * tg;
            if (nl < nrem) {
                float b2x = b2s[nl];
                float b2y = b2s[nl + 1];
                float2 r0, r1;
                r0.x = fmaxf(fmaf(-2.f, c[mt][nt][0], q2a + b2x), 0.f);
                r0.y = fmaxf(fmaf(-2.f, c[mt][nt][1], q2a + b2y), 0.f);
                r1.x = fmaxf(fmaf(-2.f, c[mt][nt][2], q2b + b2x), 0.f);
                r1.y = fmaxf(fmaf(-2.f, c[mt][nt][3], q2b + b2y), 0.f);
                size_t base = ((size_t)l * BB + m0 + ml) * NPTS + n0 + nl;
                *(float2*)&g_d2[base]               = r0;
                *(float2*)&g_d2[base + 8 * NPTS]    = r1;
            }
        }
    }
}

// ============================================================
// Kernel 4: per-(l,b) top-21 via threshold-gated candidate buffer
//   R8 config (25 KB, MLP=4) + vectorized min-gate.
// ============================================================
#define CAP 6144           // candidate buffer capacity (24 KB)
#define NF4 (NPTS / 4)     // 12500 float4 per row
#define SEEDF4 128         // first 512 elements seed the threshold
#define CHUNKF4 1024       // 4096 elements per chunk = 4 float4/thread

__global__ __launch_bounds__(256)
void topk_lid_kernel(float* __restrict__ out) {
    const int row = blockIdx.x;          // l*BB + b
    const float4* D4 = (const float4*)(g_d2 + (size_t)row * NPTS);
    const int tid = threadIdx.x;
    const int lane = tid & 31;
    const int wid = tid >> 5;

    __shared__ float buf[CAP + 32];
    __shared__ float sel[KSEL];
    __shared__ float wmin[8];
    __shared__ int   wloc[8];
    __shared__ int   cnt;
    __shared__ float tau;

    if (tid < KSEL) sel[tid] = FLT_MAX;
    if (tid == 0) cnt = 0;
    __syncthreads();

    auto merge = [&]() {
        int c = cnt;
        if (tid < KSEL) buf[c + tid] = sel[tid];
        __syncthreads();
        int total = c + KSEL;
        for (int it = 0; it < KSEL; it++) {
            float mv = FLT_MAX; int mi = 0;
            for (int i = tid; i < total; i += 256) {
                float v = buf[i];
                if (v < mv) { mv = v; mi = i; }
            }
            #pragma unroll
            for (int o = 16; o > 0; o >>= 1) {
                float ov = __shfl_xor_sync(0xFFFFFFFFu, mv, o);
                int   oi = __shfl_xor_sync(0xFFFFFFFFu, mi, o);
                if (ov < mv) { mv = ov; mi = oi; }
            }
            if (lane == 0) { wmin[wid] = mv; wloc[wid] = mi; }
            __syncthreads();
            if (tid == 0) {
                float gv = wmin[0]; int gi = wloc[0];
                #pragma unroll
                for (int w = 1; w < 8; w++)
                    if (wmin[w] < gv) { gv = wmin[w]; gi = wloc[w]; }
                sel[it] = gv;
                buf[gi] = FLT_MAX;
            }
            __syncthreads();
        }
        if (tid == 0) { tau = sel[KSEL - 1]; cnt = 0; }
        __syncthreads();
    };

    // ---- seed: first 512 elements ----
    if (tid < SEEDF4) {
        float4 v = D4[tid];
        buf[tid * 4 + 0] = v.x;
        buf[tid * 4 + 1] = v.y;
        buf[tid * 4 + 2] = v.z;
        buf[tid * 4 + 3] = v.w;
    }
    if (tid == 0) cnt = SEEDF4 * 4;
    __syncthreads();
    merge();
    float tauR = tau;

    // ---- scan rest: chunks of 1024 float4, 4 LDG.128 in flight, min-gated ----
    int base = SEEDF4;
    bool first_chunk = true;
    while (base < NF4) {
        int end = base + CHUNKF4;
        if (end > NF4) end = NF4;
        int i = base + tid;
        for (; i + 768 < end; i += 1024) {
            float4 v0 = D4[i];
            float4 v1 = D4[i + 256];
            float4 v2 = D4[i + 512];
            float4 v3 = D4[i + 768];
            float m0 = fminf(fminf(v0.x, v0.y), fminf(v0.z, v0.w));
            float m1 = fminf(fminf(v1.x, v1.y), fminf(v1.z, v1.w));
            float m2 = fminf(fminf(v2.x, v2.y), fminf(v2.z, v2.w));
            float m3 = fminf(fminf(v3.x, v3.y), fminf(v3.z, v3.w));
            float mm = fminf(fminf(m0, m1), fminf(m2, m3));
            if (mm < tauR) {
                if (m0 < tauR) {
                    if (v0.x < tauR) { int p = atomicAdd(&cnt, 1); buf[p] = v0.x; }
                    if (v0.y < tauR) { int p = atomicAdd(&cnt, 1); buf[p] = v0.y; }
                    if (v0.z < tauR) { int p = atomicAdd(&cnt, 1); buf[p] = v0.z; }
                    if (v0.w < tauR) { int p = atomicAdd(&cnt, 1); buf[p] = v0.w; }
                }
                if (m1 < tauR) {
                    if (v1.x < tauR) { int p = atomicAdd(&cnt, 1); buf[p] = v1.x; }
                    if (v1.y < tauR) { int p = atomicAdd(&cnt, 1); buf[p] = v1.y; }
                    if (v1.z < tauR) { int p = atomicAdd(&cnt, 1); buf[p] = v1.z; }
                    if (v1.w < tauR) { int p = atomicAdd(&cnt, 1); buf[p] = v1.w; }
                }
                if (m2 < tauR) {
                    if (v2.x < tauR) { int p = atomicAdd(&cnt, 1); buf[p] = v2.x; }
                    if (v2.y < tauR) { int p = atomicAdd(&cnt, 1); buf[p] = v2.y; }
                    if (v2.z < tauR) { int p = atomicAdd(&cnt, 1); buf[p] = v2.z; }
                    if (v2.w < tauR) { int p = atomicAdd(&cnt, 1); buf[p] = v2.w; }
                }
                if (m3 < tauR) {
                    if (v3.x < tauR) { int p = atomicAdd(&cnt, 1); buf[p] = v3.x; }
                    if (v3.y < tauR) { int p = atomicAdd(&cnt, 1); buf[p] = v3.y; }
                    if (v3.z < tauR) { int p = atomicAdd(&cnt, 1); buf[p] = v3.z; }
                    if (v3.w < tauR) { int p = atomicAdd(&cnt, 1); buf[p] = v3.w; }
                }
            }
        }
        for (; i < end; i += 256) {
            float4 v = D4[i];
            float m0 = fminf(fminf(v.x, v.y), fminf(v.z, v.w));
            if (m0 < tauR) {
                if (v.x < tauR) { int p = atomicAdd(&cnt, 1); buf[p] = v.x; }
                if (v.y < tauR) { int p = atomicAdd(&cnt, 1); buf[p] = v.y; }
                if (v.z < tauR) { int p = atomicAdd(&cnt, 1); buf[p] = v.z; }
                if (v.w < tauR) { int p = atomicAdd(&cnt, 1); buf[p] = v.w; }
            }
        }
        __syncthreads();
        if ((first_chunk && cnt > 0) || cnt >= CAP - 4096) {
            merge();
        }
        tauR = tau;
        first_chunk = false;
        base = end;
    }
    if (cnt > 0) merge();

    // ---- LID ----
    if (tid == 0) {
        float rk2 = sel[KSEL - 1];
        float s = 0.f;
        #pragma unroll
        for (int i = 1; i < KSEL - 1; i++)
            s += 0.5f * logf(sel[i] / rk2);
        int l = row / BB;
        int b = row % BB;
        out[b * LL + l] = -(20.0f / s);
    }
}

// ============================================================
extern "C" void kernel_launch(void* const* d_in, const int* in_sizes, int n_in,
                              void* d_out, int out_size) {
    const float* feats = (const float*)d_in[0];
    const float* bank  = (const float*)d_in[1];
    // d_in[2] (k) is fixed at 20 for this problem.

    cudaFuncSetAttribute(gemm_mma_kernel,
                         cudaFuncAttributeMaxDynamicSharedMemorySize, GEMM_DSMEM);

    qmean_kernel<<<(LL * BB * CC) / 8, 256>>>(feats);
    rowcvt_q_kernel<<<(LL * BB + 7) / 8, 256>>>();
    rowcvt_bank_kernel<<<(LL * NPTS + 7) / 8, 256>>>(bank);

    dim3 gg(2, (NPTS + Bn - 1) / Bn, LL);   // (2, 391, 4)
    gemm_mma_kernel<<<gg, 256, GEMM_DSMEM>>>();

    topk_lid_kernel<<<LL * BB, 256>>>((float*)d_out);
}

// round 13
// speedup vs baseline: 1.0624x; 1.0624x over previous
#include <cuda_runtime.h>
#include <cuda_fp16.h>
#include <math.h>
#include <float.h>
#include <stdint.h>

// Problem constants (fixed by the dataset)
#define LL 4
#define BB 256
#define CC 512
#define SS 64
#define NPTS 50000
#define KSEL 21      // k+1 smallest needed
#define SEEDN 2048   // bank prefix used to bootstrap the threshold
#define CANDCAP 4096 // per-row candidate capacity (E[count]~512, 30+ sigma)

// -------- scratch (static device globals; no runtime allocation) --------
__device__ float  g_q[LL * BB * CC];                 // 2 MB (fp32 q)
__device__ __half g_q_h[LL * BB * CC];               // 1 MB (fp16 q)
__device__ float  g_q2[LL * BB];
__device__ __half g_bank_h[(size_t)LL * NPTS * CC];  // 204.8 MB (fp16 bank)
__device__ float  g_b2[LL * NPTS];
__device__ float  g_d2s[LL * BB * SEEDN];            // 8 MB (seed d2)
__device__ float  g_tau[LL * BB];
__device__ int    g_cand_cnt[LL * BB];
__device__ float  g_cand[(size_t)LL * BB * CANDCAP]; // 16 MB

// ============================================================
// helpers
// ============================================================
__device__ __forceinline__ uint32_t smem_u32(const void* p) {
    uint32_t a;
    asm("{ .reg .u64 t; cvta.to.shared.u64 t, %1; cvt.u32.u64 %0, t; }"
        : "=r"(a) : "l"(p));
    return a;
}
__device__ __forceinline__ uint32_t h2pack(float a, float b) {
    __half2 h = __floats2half2_rn(a, b);
    return *(uint32_t*)&h;
}
__device__ __forceinline__ void cp16(uint32_t dst, const void* src, int srcsz) {
    asm volatile("cp.async.cg.shared.global [%0], [%1], 16, %2;"
                 :: "r"(dst), "l"(src), "r"(srcsz));
}
__device__ __forceinline__ void mma_f16(float* c, const uint32_t* a, const uint32_t* b) {
    asm volatile(
        "mma.sync.aligned.m16n8k16.row.col.f32.f16.f16.f32 "
        "{%0,%1,%2,%3}, {%4,%5,%6,%7}, {%8,%9}, {%0,%1,%2,%3};"
        : "+f"(c[0]), "+f"(c[1]), "+f"(c[2]), "+f"(c[3])
        : "r"(a[0]), "r"(a[1]), "r"(a[2]), "r"(a[3]), "r"(b[0]), "r"(b[1]));
}

// ============================================================
// Kernel 1: q[l,b,c] = mean_s feats[l,b,c,s]   (one warp per row of 64)
// ============================================================
__global__ void qmean_kernel(const float* __restrict__ feats) {
    int gw = (blockIdx.x * blockDim.x + threadIdx.x) >> 5;
    int lane = threadIdx.x & 31;
    if (gw >= LL * BB * CC) return;
    const float* p = feats + (size_t)gw * SS;
    float s = p[lane] + p[lane + 32];
    #pragma unroll
    for (int o = 16; o > 0; o >>= 1) s += __shfl_xor_sync(0xFFFFFFFFu, s, o);
    if (lane == 0) g_q[gw] = s * (1.0f / 64.0f);
}

// ============================================================
// Kernel 2: row convert fp32 -> fp16 + sum-of-squares (1 warp / 512-row)
// ============================================================
__device__ __forceinline__ void rowcvt_body(const float* __restrict__ src,
                                            __half* __restrict__ dst,
                                            float* __restrict__ ssq_out,
                                            int nrows) {
    int gw = (blockIdx.x * blockDim.x + threadIdx.x) >> 5;
    int lane = threadIdx.x & 31;
    if (gw >= nrows) return;
    const float4* s4 = (const float4*)(src + (size_t)gw * CC) + lane * 4;
    float4 v0 = s4[0], v1 = s4[1], v2 = s4[2], v3 = s4[3];
    float ss = 0.f;
    ss = fmaf(v0.x, v0.x, ss); ss = fmaf(v0.y, v0.y, ss);
    ss = fmaf(v0.z, v0.z, ss); ss = fmaf(v0.w, v0.w, ss);
    ss = fmaf(v1.x, v1.x, ss); ss = fmaf(v1.y, v1.y, ss);
    ss = fmaf(v1.z, v1.z, ss); ss = fmaf(v1.w, v1.w, ss);
    ss = fmaf(v2.x, v2.x, ss); ss = fmaf(v2.y, v2.y, ss);
    ss = fmaf(v2.z, v2.z, ss); ss = fmaf(v2.w, v2.w, ss);
    ss = fmaf(v3.x, v3.x, ss); ss = fmaf(v3.y, v3.y, ss);
    ss = fmaf(v3.z, v3.z, ss); ss = fmaf(v3.w, v3.w, ss);
    uint4 o0 = make_uint4(h2pack(v0.x, v0.y), h2pack(v0.z, v0.w),
                          h2pack(v1.x, v1.y), h2pack(v1.z, v1.w));
    uint4 o1 = make_uint4(h2pack(v2.x, v2.y), h2pack(v2.z, v2.w),
                          h2pack(v3.x, v3.y), h2pack(v3.z, v3.w));
    uint4* d = (uint4*)(dst + (size_t)gw * CC) + lane * 2;
    d[0] = o0; d[1] = o1;
    #pragma unroll
    for (int o = 16; o > 0; o >>= 1) ss += __shfl_xor_sync(0xFFFFFFFFu, ss, o);
    if (lane == 0) ssq_out[gw] = ss;
}
__global__ void rowcvt_q_kernel() {
    rowcvt_body(g_q, g_q_h, g_q2, LL * BB);
}
__global__ void rowcvt_bank_kernel(const float* __restrict__ bank) {
    rowcvt_body(bank, g_bank_h, g_b2, LL * NPTS);
}

// ============================================================
// Kernel 3: f16 mma GEMM (cp.async 4-stage, R11 structure)
//   mode 0: write d2 of the SEEDN prefix to g_d2s (dense)
//   mode 1: filtered epilogue -> append d2 <= tau[row] to g_cand
// ============================================================
#define Bb 128
#define Bn 128
#define Bk 16
#define STAGES 4
#define LDT2 12            // words per row (8 half2 + 4 pad, conflict-free frags)
#define TSZ2 (Bb * LDT2)   // 1536 words per stage per matrix
#define GEMM_DSMEM (STAGES * TSZ2 * 2 * 4)   // 49152 bytes

__global__ __launch_bounds__(256, 2)
void gemm_mma_kernel(int mode) {
    extern __shared__ uint32_t smw[];
    uint32_t* As = smw;                       // [stage][m][k/2]
    uint32_t* Bs = smw + STAGES * TSZ2;       // [stage][n][k/2]
    __shared__ float q2s[Bb];
    __shared__ float b2s[Bn];
    __shared__ float tau_s[Bb];

    const int l  = blockIdx.z;
    const int m0 = blockIdx.x * Bb;
    const int n0 = blockIdx.y * Bn;
    const int nrem = NPTS - n0;

    const int tid  = threadIdx.x;
    const int lane = tid & 31;
    const int wid  = tid >> 5;
    const int wm   = wid & 1;
    const int wn   = wid >> 1;
    const int gr   = lane >> 2;
    const int tg   = lane & 3;

    // cp.async loader mapping: thread t -> row t>>1, 16B-chunk t&1
    const int arow  = tid >> 1;
    const int ahalf = tid & 1;
    const bool bok  = (arow < nrem);
    const int bsz   = bok ? 16 : 0;

    const __half* ga = g_q_h    + ((size_t)(l * BB + m0) + arow) * CC + ahalf * 8;
    const __half* gb = g_bank_h + ((size_t)l * NPTS + n0 + (bok ? arow : 0)) * CC + ahalf * 8;

    const uint32_t as_u32 = smem_u32(As);
    const uint32_t bs_u32 = smem_u32(Bs);
    const uint32_t woff = (uint32_t)(arow * LDT2 + ahalf * 4);   // word offset in tile

    float c[4][4][4];
    #pragma unroll
    for (int i = 0; i < 4; i++)
        #pragma unroll
        for (int j = 0; j < 4; j++)
            #pragma unroll
            for (int t = 0; t < 4; t++) c[i][j][t] = 0.f;

    // ---- prologue: issue stages 0..2 ----
    #pragma unroll
    for (int s = 0; s < STAGES - 1; s++) {
        cp16(as_u32 + ((s * TSZ2 + woff) << 2), ga + s * Bk, 16);
        cp16(bs_u32 + ((s * TSZ2 + woff) << 2), gb + s * Bk, bsz);
        asm volatile("cp.async.commit_group;" ::: "memory");
    }

    #pragma unroll 1
    for (int i = 0; i < CC / Bk; i++) {
        asm volatile("cp.async.wait_group 2;" ::: "memory");
        __syncthreads();

        const int nx = i + STAGES - 1;
        if (nx < CC / Bk) {
            const uint32_t st = (uint32_t)(nx & (STAGES - 1)) * TSZ2;
            cp16(as_u32 + ((st + woff) << 2), ga + nx * Bk, 16);
            cp16(bs_u32 + ((st + woff) << 2), gb + nx * Bk, bsz);
        }
        asm volatile("cp.async.commit_group;" ::: "memory");

        // ---- mma on stage i&3 ----
        const uint32_t so = (uint32_t)(i & (STAGES - 1)) * TSZ2;
        uint32_t a[4][4], b[4][2];
        #pragma unroll
        for (int mt = 0; mt < 4; mt++) {
            int base = so + (wm * 64 + mt * 16 + gr) * LDT2 + tg;
            a[mt][0] = As[base];
            a[mt][1] = As[base + 8 * LDT2];
            a[mt][2] = As[base + 4];
            a[mt][3] = As[base + 8 * LDT2 + 4];
        }
        #pragma unroll
        for (int nt = 0; nt < 4; nt++) {
            int base = so + (wn * 32 + nt * 8 + gr) * LDT2 + tg;
            b[nt][0] = Bs[base];
            b[nt][1] = Bs[base + 4];
        }
        #pragma unroll
        for (int mt = 0; mt < 4; mt++)
            #pragma unroll
            for (int nt = 0; nt < 4; nt++)
                mma_f16(c[mt][nt], a[mt], b[nt]);
    }

    // ---- stage q2 / b2 / tau ----
    if (tid < Bb) {
        q2s[tid] = g_q2[l * BB + m0 + tid];
        b2s[tid] = (n0 + tid < NPTS) ? g_b2[(size_t)l * NPTS + n0 + tid] : 0.f;
        tau_s[tid] = (mode == 1) ? g_tau[l * BB + m0 + tid] : 0.f;
    }
    __syncthreads();

    if (mode == 0) {
        // ---- dense d2 of the seed prefix ----
        #pragma unroll
        for (int mt = 0; mt < 4; mt++) {
            int ml = wm * 64 + mt * 16 + gr;
            float q2a = q2s[ml];
            float q2b = q2s[ml + 8];
            #pragma unroll
            for (int nt = 0; nt < 4; nt++) {
                int nl = wn * 32 + nt * 8 + 2 * tg;
                float b2x = b2s[nl];
                float b2y = b2s[nl + 1];
                float2 r0, r1;
                r0.x = fmaxf(fmaf(-2.f, c[mt][nt][0], q2a + b2x), 0.f);
                r0.y = fmaxf(fmaf(-2.f, c[mt][nt][1], q2a + b2y), 0.f);
                r1.x = fmaxf(fmaf(-2.f, c[mt][nt][2], q2b + b2x), 0.f);
                r1.y = fmaxf(fmaf(-2.f, c[mt][nt][3], q2b + b2y), 0.f);
                size_t base = (size_t)(l * BB + m0 + ml) * SEEDN + n0 + nl;
                *(float2*)&g_d2s[base]             = r0;
                *(float2*)&g_d2s[base + 8 * SEEDN] = r1;
            }
        }
    } else {
        // ---- filtered append: d2 <= tau[row] ----
        #pragma unroll
        for (int mt = 0; mt < 4; mt++) {
            int ml = wm * 64 + mt * 16 + gr;
            float q2a = q2s[ml];
            float q2b = q2s[ml + 8];
            float ta  = tau_s[ml];
            float tb  = tau_s[ml + 8];
            int grow0 = l * BB + m0 + ml;
            int grow1 = grow0 + 8;
            #pragma unroll
            for (int nt = 0; nt < 4; nt++) {
                int nl = wn * 32 + nt * 8 + 2 * tg;
                if (nl < nrem) {
                    float b2x = b2s[nl];
                    float b2y = b2s[nl + 1];
                    float d00 = fmaxf(fmaf(-2.f, c[mt][nt][0], q2a + b2x), 0.f);
                    float d01 = fmaxf(fmaf(-2.f, c[mt][nt][1], q2a + b2y), 0.f);
                    float d10 = fmaxf(fmaf(-2.f, c[mt][nt][2], q2b + b2x), 0.f);
                    float d11 = fmaxf(fmaf(-2.f, c[mt][nt][3], q2b + b2y), 0.f);
                    if (d00 <= ta) {
                        int p = atomicAdd(&g_cand_cnt[grow0], 1);
                        if (p < CANDCAP) g_cand[(size_t)grow0 * CANDCAP + p] = d00;
                    }
                    if (d01 <= ta) {
                        int p = atomicAdd(&g_cand_cnt[grow0], 1);
                        if (p < CANDCAP) g_cand[(size_t)grow0 * CANDCAP + p] = d01;
                    }
                    if (d10 <= tb) {
                        int p = atomicAdd(&g_cand_cnt[grow1], 1);
                        if (p < CANDCAP) g_cand[(size_t)grow1 * CANDCAP + p] = d10;
                    }
                    if (d11 <= tb) {
                        int p = atomicAdd(&g_cand_cnt[grow1], 1);
                        if (p < CANDCAP) g_cand[(size_t)grow1 * CANDCAP + p] = d11;
                    }
                }
            }
        }
    }
}

// ============================================================
// Kernel 4: tau[row] = 21st smallest of seed d2; reset counters
// ============================================================
__global__ __launch_bounds__(256)
void tau_kernel() {
    const int row = blockIdx.x;
    const int tid = threadIdx.x;
    const int lane = tid & 31;
    const int wid = tid >> 5;

    __shared__ float buf[SEEDN];
    __shared__ float wmin[8];
    __shared__ int   wloc[8];
    __shared__ float last;

    for (int i = tid; i < SEEDN; i += 256)
        buf[i] = g_d2s[(size_t)row * SEEDN + i];
    __syncthreads();

    for (int it = 0; it < KSEL; it++) {
        float mv = FLT_MAX; int mi = 0;
        #pragma unroll
        for (int j = 0; j < SEEDN / 256; j++) {
            int i = tid + j * 256;
            float v = buf[i];
            if (v < mv) { mv = v; mi = i; }
        }
        #pragma unroll
        for (int o = 16; o > 0; o >>= 1) {
            float ov = __shfl_xor_sync(0xFFFFFFFFu, mv, o);
            int   oi = __shfl_xor_sync(0xFFFFFFFFu, mi, o);
            if (ov < mv) { mv = ov; mi = oi; }
        }
        if (lane == 0) { wmin[wid] = mv; wloc[wid] = mi; }
        __syncthreads();
        if (tid == 0) {
            float gv = wmin[0]; int gi = wloc[0];
            #pragma unroll
            for (int w = 1; w < 8; w++)
                if (wmin[w] < gv) { gv = wmin[w]; gi = wloc[w]; }
            last = gv;
            buf[gi] = FLT_MAX;
        }
        __syncthreads();
    }
    if (tid == 0) {
        g_tau[row] = last;
        g_cand_cnt[row] = 0;
    }
}

// ============================================================
// Kernel 5: final top-21 over candidates + LID
// ============================================================
__global__ __launch_bounds__(256)
void lid_final_kernel(float* __restrict__ out) {
    const int row = blockIdx.x;
    const int tid = threadIdx.x;
    const int lane = tid & 31;
    const int wid = tid >> 5;

    __shared__ float buf[CANDCAP];
    __shared__ float sel[KSEL];
    __shared__ float wmin[8];
    __shared__ int   wloc[8];

    int cnt = g_cand_cnt[row];
    if (cnt > CANDCAP) cnt = CANDCAP;
    for (int i = tid; i < cnt; i += 256)
        buf[i] = g_cand[(size_t)row * CANDCAP + i];
    __syncthreads();

    for (int it = 0; it < KSEL; it++) {
        float mv = FLT_MAX; int mi = 0;
        for (int i = tid; i < cnt; i += 256) {
            float v = buf[i];
            if (v < mv) { mv = v; mi = i; }
        }
        #pragma unroll
        for (int o = 16; o > 0; o >>= 1) {
            float ov = __shfl_xor_sync(0xFFFFFFFFu, mv, o);
            int   oi = __shfl_xor_sync(0xFFFFFFFFu, mi, o);
            if (ov < mv) { mv = ov; mi = oi; }
        }
        if (lane == 0) { wmin[wid] = mv; wloc[wid] = mi; }
        __syncthreads();
        if (tid == 0) {
            float gv = wmin[0]; int gi = wloc[0];
            #pragma unroll
            for (int w = 1; w < 8; w++)
                if (wmin[w] < gv) { gv = wmin[w]; gi = wloc[w]; }
            sel[it] = gv;
            buf[gi] = FLT_MAX;
        }
        __syncthreads();
    }

    if (tid == 0) {
        float rk2 = sel[KSEL - 1];
        float s = 0.f;
        #pragma unroll
        for (int i = 1; i < KSEL - 1; i++)
            s += 0.5f * logf(sel[i] / rk2);
        int l = row / BB;
        int b = row % BB;
        out[b * LL + l] = -(20.0f / s);
    }
}

// ============================================================
extern "C" void kernel_launch(void* const* d_in, const int* in_sizes, int n_in,
                              void* d_out, int out_size) {
    const float* feats = (const float*)d_in[0];
    const float* bank  = (const float*)d_in[1];
    // d_in[2] (k) is fixed at 20 for this problem.

    cudaFuncSetAttribute(gemm_mma_kernel,
                         cudaFuncAttributeMaxDynamicSharedMemorySize, GEMM_DSMEM);

    qmean_kernel<<<(LL * BB * CC) / 8, 256>>>(feats);
    rowcvt_q_kernel<<<(LL * BB + 7) / 8, 256>>>();
    rowcvt_bank_kernel<<<(LL * NPTS + 7) / 8, 256>>>(bank);

    dim3 gseed(2, SEEDN / Bn, LL);          // (2, 16, 4)
    gemm_mma_kernel<<<gseed, 256, GEMM_DSMEM>>>(0);

    tau_kernel<<<LL * BB, 256>>>();

    dim3 gfull(2, (NPTS + Bn - 1) / Bn, LL); // (2, 391, 4)
    gemm_mma_kernel<<<gfull, 256, GEMM_DSMEM>>>(1);

    lid_final_kernel<<<LL * BB, 256>>>((float*)d_out);
}